// round 13
// baseline (speedup 1.0000x reference)
#include <cuda_runtime.h>
#include <cstdint>

#define N0    512000
#define IN_F  128
#define HID   256
#define OUT_F 64
#define NN1   20480
#define NN2   2048
#define NE1   512000
#define NE2   20480
#define EPSV  1e-4f

// ---------------- device scratch ----------------
__device__ float    g_alpha1[N0];
__device__ uint4    g_mask1[N0];      // word w bit L = col 8*(L&15)+(L>>4)+2w
__device__ unsigned g_cnt1[NN1];      // zero-init; scan re-zeroes after use
__device__ unsigned g_off1[NN1 + 1];
__device__ unsigned g_cur1[NN1];
__device__ int      g_srcs1[NE1];
__device__ float    g_agg1[NN1 * IN_F];
__device__ float    g_alpha2[NN1];
__device__ unsigned g_mask2[NN1 * 8]; // word q bit b = col 32q+b
__device__ unsigned g_cnt2[NN2];
__device__ unsigned g_off2[NN2 + 1];
__device__ unsigned g_cur2[NN2];
__device__ int      g_srcs2[NE2];
__device__ float    g_bt1[IN_F * HID];  // w_hat_rel1 transposed [k=128][n=256]
__device__ float    g_mroot1[HID];
__device__ uint4    g_wmask1[HID];      // same layout as g_mask1
__device__ float    g_bsum1[HID];
__device__ float    g_bt2[HID * OUT_F]; // [256][64]
__device__ float    g_mroot2[OUT_F];
__device__ unsigned g_wmask2[OUT_F * 8];// word q bit L = col 32q+L
__device__ float    g_bsum2[OUT_F];

// ---------------- helpers ----------------
typedef unsigned long long ull;
__device__ __forceinline__ float warp_sum(float v) {
#pragma unroll
    for (int o = 16; o; o >>= 1) v += __shfl_xor_sync(0xffffffffu, v, o);
    return v;
}
__device__ __forceinline__ float half_sum(float v) {
#pragma unroll
    for (int o = 8; o; o >>= 1) v += __shfl_xor_sync(0xffffffffu, v, o);
    return v;
}
__device__ __forceinline__ float warp_max(float v) {
#pragma unroll
    for (int o = 16; o; o >>= 1) v = fmaxf(v, __shfl_xor_sync(0xffffffffu, v, o));
    return v;
}
__device__ __forceinline__ ull bcast2(float a) {
    ull r;
    asm("mov.b64 %0, {%1, %1};" : "=l"(r) : "f"(a));
    return r;
}
__device__ __forceinline__ ull pack2(float lo, float hi) {
    ull r;
    asm("mov.b64 %0, {%1, %2};" : "=l"(r) : "f"(lo), "f"(hi));
    return r;
}
__device__ __forceinline__ void fma2(ull& c, ull a, ull b) {
    asm("fma.rn.f32x2 %0, %1, %2, %0;" : "+l"(c) : "l"(a), "l"(b));
}
__device__ __forceinline__ ull add2(ull a, ull b) {
    ull r;
    asm("add.rn.f32x2 %0, %1, %2;" : "=l"(r) : "l"(a), "l"(b));
    return r;
}
__device__ __forceinline__ ull mul2(ull a, ull b) {
    ull r;
    asm("mul.rn.f32x2 %0, %1, %2;" : "=l"(r) : "l"(a), "l"(b));
    return r;
}
__device__ __forceinline__ void unpack2(ull v, float& lo, float& hi) {
    asm("mov.b64 {%0, %1}, %2;" : "=f"(lo), "=f"(hi) : "l"(v));
}
__device__ __forceinline__ int popc4(uint4 a, uint4 b) {
    return __popc(a.x ^ b.x) + __popc(a.y ^ b.y) + __popc(a.z ^ b.z) + __popc(a.w ^ b.w);
}
__device__ __forceinline__ uint32_t smem_u32(const void* p) {
    uint32_t a;
    asm("{ .reg .u64 t; cvta.to.shared.u64 t, %1; cvt.u32.u64 %0, t; }" : "=r"(a) : "l"(p));
    return a;
}
__device__ __forceinline__ void cp16(uint32_t d, const void* s) {
    asm volatile("cp.async.ca.shared.global [%0], [%1], 16;" :: "r"(d), "l"(s) : "memory");
}
#define CP_COMMIT() asm volatile("cp.async.commit_group;" ::: "memory")
#define CP_WAIT(n)  asm volatile("cp.async.wait_group %0;" :: "n"(n) : "memory")

// ---------------- mega: hist [0,260) + prep [260,300) + binact [300,16300) --
__global__ __launch_bounds__(512) void mega_kernel(
    const float* __restrict__ x,
    const int* __restrict__ dst1, const int* __restrict__ dst2,
    const float* __restrict__ wr1, const float* __restrict__ wroot1,
    const float* __restrict__ wr2, const float* __restrict__ wroot2,
    const float* __restrict__ brel1, const float* __restrict__ broot1,
    const float* __restrict__ brel2, const float* __restrict__ broot2)
{
    unsigned bid = blockIdx.x;
    int tid = threadIdx.x;
    if (bid < 260u) {                       // ---- hist ----
        unsigned t = bid * 512u + tid;
        if (t < NE1 / 4) {
            int4 d = ((const int4*)dst1)[t];
            atomicAdd(&g_cnt1[d.x], 1u); atomicAdd(&g_cnt1[d.y], 1u);
            atomicAdd(&g_cnt1[d.z], 1u); atomicAdd(&g_cnt1[d.w], 1u);
        } else {
            unsigned j = t - NE1 / 4;
            if (j < NE2 / 4) {
                int4 d = ((const int4*)dst2)[j];
                atomicAdd(&g_cnt2[d.x], 1u); atomicAdd(&g_cnt2[d.y], 1u);
                atomicAdd(&g_cnt2[d.z], 1u); atomicAdd(&g_cnt2[d.w], 1u);
            }
        }
        return;
    }
    if (bid < 300u) {                       // ---- prep ----
        int t = (bid - 260u) * 512 + tid;   // 0..20479
        if (t < HID) g_bsum1[t] = brel1[t] + broot1[t];
        if (t < OUT_F) g_bsum2[t] = brel2[t] + broot2[t];
        int w = t >> 5;
        int L = tid & 31;
        if (w < HID) {                      // rel1 -> fp32 w_hat transposed
            int k = w;
            float4 v = *(const float4*)(wr1 + (size_t)k * IN_F + 4 * L);
            float s = warp_sum(fabsf(v.x) + fabsf(v.y) + fabsf(v.z) + fabsf(v.w));
            float m = s * (1.f / IN_F);
            float vv[4] = {v.x, v.y, v.z, v.w};
#pragma unroll
            for (int q = 0; q < 4; q++) {
                int j = 4 * L + q;
                g_bt1[j * HID + k] = vv[q] > 0.f ? m : (vv[q] < 0.f ? -m : 0.f);
            }
        } else if (w < 2 * HID) {           // root1 -> masks (binact layout) + mroot
            int k = w - HID;
            int cb = 8 * (L & 15) + (L >> 4);
            float f0 = wroot1[(size_t)k * IN_F + cb];
            float f1 = wroot1[(size_t)k * IN_F + cb + 2];
            float f2 = wroot1[(size_t)k * IN_F + cb + 4];
            float f3 = wroot1[(size_t)k * IN_F + cb + 6];
            float s = warp_sum(fabsf(f0) + fabsf(f1) + fabsf(f2) + fabsf(f3));
            unsigned b0 = __ballot_sync(0xffffffffu, f0 > 0.f);
            unsigned b1 = __ballot_sync(0xffffffffu, f1 > 0.f);
            unsigned b2 = __ballot_sync(0xffffffffu, f2 > 0.f);
            unsigned b3 = __ballot_sync(0xffffffffu, f3 > 0.f);
            if (L == 0) {
                g_mroot1[k] = s * (1.f / IN_F);
                g_wmask1[k] = make_uint4(b0, b1, b2, b3);
            }
        } else if (w < 2 * HID + OUT_F) {   // rel2 -> fp32 bt2
            int k = w - 2 * HID;
            float4 u = *(const float4*)(wr2 + (size_t)k * HID + 8 * L);
            float4 v = *(const float4*)(wr2 + (size_t)k * HID + 8 * L + 4);
            float s = warp_sum(fabsf(u.x) + fabsf(u.y) + fabsf(u.z) + fabsf(u.w) +
                               fabsf(v.x) + fabsf(v.y) + fabsf(v.z) + fabsf(v.w));
            float m = s * (1.f / HID);
            float vv[8] = {u.x, u.y, u.z, u.w, v.x, v.y, v.z, v.w};
#pragma unroll
            for (int q = 0; q < 8; q++) {
                int j = 8 * L + q;
                g_bt2[j * OUT_F + k] = vv[q] > 0.f ? m : (vv[q] < 0.f ? -m : 0.f);
            }
        } else if (w < 2 * HID + 2 * OUT_F) { // root2 -> masks: word q bit L = col 32q+L
            int k = w - 2 * HID - OUT_F;
            float s = 0.f;
            unsigned b[8];
#pragma unroll
            for (int q = 0; q < 8; q++) {
                float f = wroot2[(size_t)k * HID + 32 * q + L];
                s += fabsf(f);
                b[q] = __ballot_sync(0xffffffffu, f > 0.f);
            }
            s = warp_sum(s);
            if (L == 0) {
                g_mroot2[k] = s * (1.f / HID);
#pragma unroll
                for (int q = 0; q < 8; q++) g_wmask2[k * 8 + q] = b[q];
            }
        }
        return;
    }
    // ---- binact1: 2 rows per warp (16 lanes x 8 elems), f32x2 lane math ----
    int w = tid >> 5, L = tid & 31;
    int hl = L & 15, ph = L >> 4;
    int row = (bid - 300u) * 32 + 2 * w + ph;
    const float* xr = x + (size_t)row * IN_F + 8 * hl;
    float4 v1 = *(const float4*)xr;
    float4 v2 = *(const float4*)(xr + 4);
    ull p01 = pack2(v1.x, v1.y), p23 = pack2(v1.z, v1.w);
    ull p45 = pack2(v2.x, v2.y), p67 = pack2(v2.z, v2.w);
    ull s2 = add2(add2(p01, p23), add2(p45, p67));
    ull q2 = mul2(p01, p01);
    fma2(q2, p23, p23);
    fma2(q2, p45, p45);
    fma2(q2, p67, p67);
    float sl, sh, ql, qh;
    unpack2(s2, sl, sh);
    unpack2(q2, ql, qh);
    float s = half_sum(sl + sh);
    float sq = half_sum(ql + qh);
    float mu = s * (1.f / 128.f);
    float var = (sq - 128.f * mu * mu) * (1.f / 127.f);
    float sd = sqrtf(fmaxf(var, 0.f));
    ull nmu2 = bcast2(-mu);
    ull d01 = add2(p01, nmu2), d23 = add2(p23, nmu2);
    ull d45 = add2(p45, nmu2), d67 = add2(p67, nmu2);
    float e0, e1, e2, e3, e4, e5, e6, e7;
    unpack2(d01, e0, e1); unpack2(d23, e2, e3);
    unpack2(d45, e4, e5); unpack2(d67, e6, e7);
    float l1 = fabsf(e0) + fabsf(e1) + fabsf(e2) + fabsf(e3) +
               fabsf(e4) + fabsf(e5) + fabsf(e6) + fabsf(e7);
    l1 = half_sum(l1);
    float a = (l1 * (1.f / 128.f)) / (sd + EPSV);
    unsigned b0 = __ballot_sync(0xffffffffu, v1.x > mu);
    unsigned b1 = __ballot_sync(0xffffffffu, v1.y > mu);
    unsigned b2 = __ballot_sync(0xffffffffu, v1.z > mu);
    unsigned b3 = __ballot_sync(0xffffffffu, v1.w > mu);
    unsigned b4 = __ballot_sync(0xffffffffu, v2.x > mu);
    unsigned b5 = __ballot_sync(0xffffffffu, v2.y > mu);
    unsigned b6 = __ballot_sync(0xffffffffu, v2.z > mu);
    unsigned b7 = __ballot_sync(0xffffffffu, v2.w > mu);
    if (L == 0) {
        g_alpha1[row] = a;
        g_mask1[row] = make_uint4((b0 & 0xFFFFu) | (b1 << 16),
                                  (b2 & 0xFFFFu) | (b3 << 16),
                                  (b4 & 0xFFFFu) | (b5 << 16),
                                  (b6 & 0xFFFFu) | (b7 << 16));
    } else if (L == 16) {
        g_alpha1[row] = a;
        g_mask1[row] = make_uint4((b0 >> 16) | (b1 & 0xFFFF0000u),
                                  (b2 >> 16) | (b3 & 0xFFFF0000u),
                                  (b4 >> 16) | (b5 & 0xFFFF0000u),
                                  (b6 >> 16) | (b7 & 0xFFFF0000u));
    }
}

// ---------------- scan (both layers); re-zeroes cnt for replay ----------------
__global__ __launch_bounds__(1024) void scan12_kernel() {
    int layer = blockIdx.x;
    unsigned* cnt = layer ? g_cnt2 : g_cnt1;
    unsigned* off = layer ? g_off2 : g_off1;
    unsigned* cur = layer ? g_cur2 : g_cur1;
    int n = layer ? NN2 : NN1;
    int per = n >> 10;
    int t = threadIdx.x;
    int s0 = t * per;
    unsigned loc[20];
    unsigned tot = 0;
    for (int i = 0; i < per; i++) { loc[i] = cnt[s0 + i]; cnt[s0 + i] = 0u; tot += loc[i]; }
    unsigned ws = tot;
#pragma unroll
    for (int o = 1; o < 32; o <<= 1) {
        unsigned u = __shfl_up_sync(0xffffffffu, ws, o);
        if ((t & 31) >= o) ws += u;
    }
    __shared__ unsigned wsum[32];
    if ((t & 31) == 31) wsum[t >> 5] = ws;
    __syncthreads();
    if (t < 32) {
        unsigned v2 = wsum[t], sc = v2;
#pragma unroll
        for (int o = 1; o < 32; o <<= 1) {
            unsigned u = __shfl_up_sync(0xffffffffu, sc, o);
            if (t >= o) sc += u;
        }
        wsum[t] = sc - v2;
    }
    __syncthreads();
    unsigned run = wsum[t >> 5] + ws - tot;
    for (int i = 0; i < per; i++) {
        off[s0 + i] = run;
        cur[s0 + i] = run;
        run += loc[i];
    }
    if (t == 1023) off[n] = run;
}

// ---------------- placement (4 edges/thread) ----------------
__global__ __launch_bounds__(512) void place12_kernel(
    const int* __restrict__ dst1, const int* __restrict__ src1,
    const int* __restrict__ dst2, const int* __restrict__ src2)
{
    unsigned t = blockIdx.x * 512u + threadIdx.x;
    if (t < NE1 / 4) {
        int4 d = ((const int4*)dst1)[t];
        int4 s = ((const int4*)src1)[t];
        g_srcs1[atomicAdd(&g_cur1[d.x], 1u)] = s.x;
        g_srcs1[atomicAdd(&g_cur1[d.y], 1u)] = s.y;
        g_srcs1[atomicAdd(&g_cur1[d.z], 1u)] = s.z;
        g_srcs1[atomicAdd(&g_cur1[d.w], 1u)] = s.w;
    } else {
        unsigned j = t - NE1 / 4;
        if (j < NE2 / 4) {
            int4 d = ((const int4*)dst2)[j];
            int4 s = ((const int4*)src2)[j];
            g_srcs2[atomicAdd(&g_cur2[d.x], 1u)] = s.x;
            g_srcs2[atomicAdd(&g_cur2[d.y], 1u)] = s.y;
            g_srcs2[atomicAdd(&g_cur2[d.z], 1u)] = s.z;
            g_srcs2[atomicAdd(&g_cur2[d.w], 1u)] = s.w;
        }
    }
}

// ---------------- agg1: one dst per warp; sign-trick accumulation ----------
__global__ __launch_bounds__(256) void agg1_kernel() {
    int d = (blockIdx.x * 256 + threadIdx.x) >> 5;
    int L = threadIdx.x & 31;
    unsigned beg = g_off1[d], end = g_off1[d + 1];
    float a0 = 0.f, a1 = 0.f, a2 = 0.f, a3 = 0.f, asum = 0.f;
    for (unsigned base = beg; base < end; base += 32u) {
        unsigned e = base + L;
        float al = 0.f;
        uint4 m = make_uint4(0u, 0u, 0u, 0u);
        if (e < end) {
            int s = g_srcs1[e];
            al = g_alpha1[s];
            m = g_mask1[s];
        }
        unsigned n = min(32u, end - base);
        for (unsigned t2 = 0; t2 < n; t2++) {
            float av = __shfl_sync(0xffffffffu, al, t2);
            unsigned mx = __shfl_sync(0xffffffffu, m.x, t2);
            unsigned my = __shfl_sync(0xffffffffu, m.y, t2);
            unsigned mz = __shfl_sync(0xffffffffu, m.z, t2);
            unsigned mw = __shfl_sync(0xffffffffu, m.w, t2);
            asum += av;
            if ((mx >> L) & 1u) a0 += av;
            if ((my >> L) & 1u) a1 += av;
            if ((mz >> L) & 1u) a2 += av;
            if ((mw >> L) & 1u) a3 += av;
        }
    }
    unsigned c = end - beg;
    float inv = 1.f / (float)(c == 0u ? 1u : c);
    // a_c = 2*acc - asum  (sum of +-alpha)
    a0 = (2.f * a0 - asum) * inv;
    a1 = (2.f * a1 - asum) * inv;
    a2 = (2.f * a2 - asum) * inv;
    a3 = (2.f * a3 - asum) * inv;
    // bit L of word w <-> col 8*(L&15)+(L>>4)+2w
    int cb = 8 * (L & 15) + (L >> 4);
    float* o = g_agg1 + (size_t)d * IN_F;
    o[cb]     = a0;
    o[cb + 2] = a1;
    o[cb + 4] = a2;
    o[cb + 6] = a3;
}

// ---------------- gemm1: A pre-duplicated k-major, 8 rows x 2 cols/thread ----
#define SMA2  0                        // ull As2[128][32]       32768 B
#define SMB   32768                    // float Bs[2][16][256]   32768 B
#define SMRS  65536                    // float2 redS[32][4]     1024 B
#define SMRL  66560                    // float  redL[32][4]     512 B
#define SMSK  67072                    // unsigned smask[32][8]  1024 B
#define SMT   68096

__global__ __launch_bounds__(512, 2) void gemm1_kernel() {
    extern __shared__ char sm[];
    ull (*As2)[32]       = (ull (*)[32])(sm + SMA2);
    float2 (*redS)[4]    = (float2 (*)[4])(sm + SMRS);
    float (*redL)[4]     = (float (*)[4])(sm + SMRL);
    unsigned (*smask)[8] = (unsigned (*)[8])(sm + SMSK);
    uint32_t sb = smem_u32(sm);
    int tid = threadIdx.x;
    int w = tid >> 5, L = tid & 31;
    int rg = w & 3, cg = w >> 2;       // 4 row-groups x 4 col-groups
    int bm = blockIdx.x * 32;
    if (tid < 256) smask[tid >> 3][tid & 7] = 0u;

    // stage A: k-major, each value duplicated into an f32x2 pair
#pragma unroll
    for (int r = 0; r < 2; r++) {
        int idx = tid + r * 512;
        int row = idx & 31, kq = idx >> 5;    // kq 0..31
        float4 v = *(const float4*)(g_agg1 + (size_t)(bm + row) * IN_F + 4 * kq);
        As2[4 * kq + 0][row] = pack2(v.x, v.x);
        As2[4 * kq + 1][row] = pack2(v.y, v.y);
        As2[4 * kq + 2][row] = pack2(v.z, v.z);
        As2[4 * kq + 3][row] = pack2(v.w, v.w);
    }
    // prefetch B chunk 0
#pragma unroll
    for (int r = 0; r < 2; r++) {
        int idx = tid + r * 512;
        int kk = idx >> 6, n4 = idx & 63;
        cp16(sb + SMB + (unsigned)kk * 1024u + 16u * n4,
             g_bt1 + (size_t)kk * HID + 4 * n4);
    }
    CP_COMMIT();

    ull acc[8];
#pragma unroll
    for (int i = 0; i < 8; i++) acc[i] = 0ull;
    int coff = cg * 64 + 2 * L;

    for (int k0 = 0; k0 < 8; k0++) {
        int cur = k0 & 1;
        if (k0 < 7) {
#pragma unroll
            for (int r = 0; r < 2; r++) {
                int idx = tid + r * 512;
                int kk = idx >> 6, n4 = idx & 63;
                cp16(sb + SMB + (unsigned)((cur ^ 1) * 16 + kk) * 1024u + 16u * n4,
                     g_bt1 + (size_t)((k0 + 1) * 16 + kk) * HID + 4 * n4);
            }
            CP_COMMIT();
            CP_WAIT(1);
        } else {
            CP_WAIT(0);
        }
        __syncthreads();
        const float* bb = (const float*)(sm + SMB + (unsigned)cur * 16384u);
#pragma unroll
        for (int kk = 0; kk < 16; kk++) {
            ull bv = *(const ull*)(bb + kk * 256 + coff);
            const ull* arow = &As2[k0 * 16 + kk][rg * 8];
#pragma unroll
            for (int i = 0; i < 8; i++) fma2(acc[i], arow[i], bv);
        }
        __syncthreads();
    }

    // ---- epilogue: root + bias + relu + binact2 (2 cols x 8 rows) ----
    int c0 = coff;
    float mr0 = g_mroot1[c0], mr1 = g_mroot1[c0 + 1];
    float bs0 = g_bsum1[c0], bs1 = g_bsum1[c0 + 1];
    uint4 wm0 = g_wmask1[c0], wm1 = g_wmask1[c0 + 1];
    float v0[8], v1[8];
#pragma unroll
    for (int i = 0; i < 8; i++) {
        int row = bm + rg * 8 + i;
        float al = g_alpha1[row];
        uint4 mx = g_mask1[row];
        unpack2(acc[i], v0[i], v1[i]);
        int p0 = popc4(mx, wm0);
        int p1 = popc4(mx, wm1);
        float a2r = al * mr0;
        float b2r = al * mr1;
        v0[i] = fmaxf(v0[i] + bs0 + a2r * (float)(128 - 2 * p0), 0.f);
        v1[i] = fmaxf(v1[i] + bs1 + b2r * (float)(128 - 2 * p1), 0.f);
        float ss = warp_sum(v0[i] + v1[i]);
        float qq = warp_sum(fmaf(v0[i], v0[i], v1[i] * v1[i]));
        if (L == 0) redS[rg * 8 + i][cg] = make_float2(ss, qq);
    }
    __syncthreads();
#pragma unroll
    for (int i = 0; i < 8; i++) {
        int r = rg * 8 + i;
        float2 r0 = redS[r][0], r1 = redS[r][1], r2 = redS[r][2], r3 = redS[r][3];
        float mu = (r0.x + r1.x + r2.x + r3.x) * (1.f / 256.f);
        float d0 = v0[i] - mu, d1 = v1[i] - mu;
        float l1 = warp_sum(fabsf(d0) + fabsf(d1));
        if (L == 0) redL[r][cg] = l1;
        unsigned bits = ((d0 > 0.f) ? 1u : 0u) | ((d1 > 0.f) ? 2u : 0u);
        bits <<= 2 * (L & 15);
        atomicOr(&smask[r][cg * 2 + (L >> 4)], bits);
    }
    __syncthreads();
    if (tid < 32) {
        int r = tid;
        float2 r0 = redS[r][0], r1 = redS[r][1], r2 = redS[r][2], r3 = redS[r][3];
        float S = r0.x + r1.x + r2.x + r3.x;
        float Q = r0.y + r1.y + r2.y + r3.y;
        float mu = S * (1.f / 256.f);
        float var = (Q - 256.f * mu * mu) * (1.f / 255.f);
        float sd = sqrtf(fmaxf(var, 0.f));
        float L1 = redL[r][0] + redL[r][1] + redL[r][2] + redL[r][3];
        g_alpha2[bm + r] = (L1 * (1.f / 256.f)) / (sd + EPSV);
        uint4* mp = (uint4*)(g_mask2 + (size_t)(bm + r) * 8);
        mp[0] = make_uint4(smask[r][0], smask[r][1], smask[r][2], smask[r][3]);
        mp[1] = make_uint4(smask[r][4], smask[r][5], smask[r][6], smask[r][7]);
    }
}

// ---------------- fused agg2 + gemm2 + root + log_softmax ----------------
__global__ __launch_bounds__(256) void aggfinal_kernel(float* __restrict__ out) {
    __shared__ float sa[8][264];
    __shared__ float bts[64][72];
    int tid = threadIdx.x;
    int w = tid >> 5, L = tid & 31;
    int d = blockIdx.x * 8 + w;

    unsigned beg = g_off2[d], end = g_off2[d + 1];
    float a[8];
    float asum = 0.f;
#pragma unroll
    for (int q = 0; q < 8; q++) a[q] = 0.f;
    for (unsigned base = beg; base < end; base += 32u) {
        unsigned e = base + L;
        float al = 0.f;
        uint4 m1 = make_uint4(0u, 0u, 0u, 0u), m2 = m1;
        if (e < end) {
            int s = g_srcs2[e];
            al = g_alpha2[s];
            const uint4* mp = (const uint4*)(g_mask2 + (size_t)s * 8);
            m1 = mp[0]; m2 = mp[1];
        }
        unsigned n = min(32u, end - base);
        for (unsigned t = 0; t < n; t++) {
            float av = __shfl_sync(0xffffffffu, al, t);
            unsigned mw0 = __shfl_sync(0xffffffffu, m1.x, t);
            unsigned mw1 = __shfl_sync(0xffffffffu, m1.y, t);
            unsigned mw2 = __shfl_sync(0xffffffffu, m1.z, t);
            unsigned mw3 = __shfl_sync(0xffffffffu, m1.w, t);
            unsigned mw4 = __shfl_sync(0xffffffffu, m2.x, t);
            unsigned mw5 = __shfl_sync(0xffffffffu, m2.y, t);
            unsigned mw6 = __shfl_sync(0xffffffffu, m2.z, t);
            unsigned mw7 = __shfl_sync(0xffffffffu, m2.w, t);
            asum += av;
            if ((mw0 >> L) & 1u) a[0] += av;
            if ((mw1 >> L) & 1u) a[1] += av;
            if ((mw2 >> L) & 1u) a[2] += av;
            if ((mw3 >> L) & 1u) a[3] += av;
            if ((mw4 >> L) & 1u) a[4] += av;
            if ((mw5 >> L) & 1u) a[5] += av;
            if ((mw6 >> L) & 1u) a[6] += av;
            if ((mw7 >> L) & 1u) a[7] += av;
        }
    }
    unsigned c = end - beg;
    float inv = 1.f / (float)(c == 0u ? 1u : c);
#pragma unroll
    for (int q = 0; q < 8; q++) sa[w][32 * q + L] = (2.f * a[q] - asum) * inv;

    float acc0 = 0.f, acc1 = 0.f;
    for (int j0 = 0; j0 < HID; j0 += 64) {
        __syncthreads();
#pragma unroll
        for (int r = 0; r < 4; r++) {
            int f = tid + r * 256;
            int jj = f >> 4, c4 = f & 15;
            *(float4*)&bts[jj][c4 * 4] =
                *(const float4*)(g_bt2 + (size_t)(j0 + jj) * OUT_F + 4 * c4);
        }
        __syncthreads();
#pragma unroll 8
        for (int jj = 0; jj < 64; jj++) {
            float av = sa[w][j0 + jj];
            acc0 = fmaf(av, bts[jj][L], acc0);
            acc1 = fmaf(av, bts[jj][L + 32], acc1);
        }
    }

    int c0 = L, c1 = L + 32;
    const uint4* mp = (const uint4*)(g_mask2 + (size_t)d * 8);
    uint4 ma = mp[0], mb = mp[1];
    float al = g_alpha2[d];
    const uint4* w0 = (const uint4*)(g_wmask2 + c0 * 8);
    const uint4* w1 = (const uint4*)(g_wmask2 + c1 * 8);
    int p0 = popc4(ma, w0[0]) + popc4(mb, w0[1]);
    int p1 = popc4(ma, w1[0]) + popc4(mb, w1[1]);
    float v0 = acc0 + g_bsum2[c0] + al * g_mroot2[c0] * (float)(256 - 2 * p0);
    float v1 = acc1 + g_bsum2[c1] + al * g_mroot2[c1] * (float)(256 - 2 * p1);
    float mx = warp_max(fmaxf(v0, v1));
    float s = warp_sum(expf(v0 - mx) + expf(v1 - mx));
    float lse = mx + logf(s);
    out[(size_t)d * OUT_F + c0] = v0 - lse;
    out[(size_t)d * OUT_F + c1] = v1 - lse;
}

// ---------------- launcher ----------------
extern "C" void kernel_launch(void* const* d_in, const int* in_sizes, int n_in,
                              void* d_out, int out_size) {
    const float* x       = (const float*)d_in[0];
    const int*   src1    = (const int*)d_in[1];
    const int*   dst1    = (const int*)d_in[2];
    const int*   src2    = (const int*)d_in[3];
    const int*   dst2    = (const int*)d_in[4];
    const float* w_rel1  = (const float*)d_in[5];
    const float* b_rel1  = (const float*)d_in[6];
    const float* w_root1 = (const float*)d_in[7];
    const float* b_root1 = (const float*)d_in[8];
    const float* w_rel2  = (const float*)d_in[9];
    const float* b_rel2  = (const float*)d_in[10];
    const float* w_root2 = (const float*)d_in[11];
    const float* b_root2 = (const float*)d_in[12];
    float* out = (float*)d_out;

    static int once = 0;
    if (!once) {
        cudaFuncSetAttribute(gemm1_kernel,
                             cudaFuncAttributeMaxDynamicSharedMemorySize, SMT);
        once = 1;
    }

    mega_kernel<<<16300, 512>>>(x, dst1, dst2, w_rel1, w_root1, w_rel2, w_root2,
                                b_rel1, b_root1, b_rel2, b_root2);
    scan12_kernel<<<2, 1024>>>();
    place12_kernel<<<260, 512>>>(dst1, src1, dst2, src2);
    agg1_kernel<<<NN1 * 32 / 256, 256>>>();
    gemm1_kernel<<<NN1 / 32, 512, SMT>>>();
    aggfinal_kernel<<<NN2 / 8, 256>>>(out);
    (void)in_sizes; (void)n_in; (void)out_size;
}

// round 14
// speedup vs baseline: 1.1510x; 1.1510x over previous
#include <cuda_runtime.h>
#include <cstdint>

#define N0    512000
#define IN_F  128
#define HID   256
#define OUT_F 64
#define NN1   20480
#define NN2   2048
#define NE1   512000
#define NE2   20480
#define EPSV  1e-4f

// ---------------- device scratch ----------------
__device__ float    g_alpha1[N0];
__device__ uint4    g_mask1[N0];      // word w bit L = col 8*(L&15)+(L>>4)+2w
__device__ unsigned g_cnt1[NN1];      // zero-init; scan re-zeroes after use
__device__ unsigned g_off1[NN1 + 1];
__device__ unsigned g_cur1[NN1];
__device__ int      g_srcs1[NE1];
__device__ float    g_agg1[NN1 * IN_F];
__device__ float    g_alpha2[NN1];
__device__ unsigned g_mask2[NN1 * 8]; // word q bit b = col 32q+b
__device__ unsigned g_cnt2[NN2];
__device__ unsigned g_off2[NN2 + 1];
__device__ unsigned g_cur2[NN2];
__device__ int      g_srcs2[NE2];
__device__ float    g_bt1[IN_F * HID];  // w_hat_rel1 transposed [k=128][n=256]
__device__ float    g_mroot1[HID];
__device__ uint4    g_wmask1[HID];      // same layout as g_mask1
__device__ float    g_bsum1[HID];
__device__ float    g_bt2[HID * OUT_F]; // [256][64]
__device__ float    g_mroot2[OUT_F];
__device__ unsigned g_wmask2[OUT_F * 8];// word q bit L = col 32q+L
__device__ float    g_bsum2[OUT_F];

// ---------------- helpers ----------------
typedef unsigned long long ull;
__device__ __forceinline__ float warp_sum(float v) {
#pragma unroll
    for (int o = 16; o; o >>= 1) v += __shfl_xor_sync(0xffffffffu, v, o);
    return v;
}
__device__ __forceinline__ float half_sum(float v) {
#pragma unroll
    for (int o = 8; o; o >>= 1) v += __shfl_xor_sync(0xffffffffu, v, o);
    return v;
}
__device__ __forceinline__ float warp_max(float v) {
#pragma unroll
    for (int o = 16; o; o >>= 1) v = fmaxf(v, __shfl_xor_sync(0xffffffffu, v, o));
    return v;
}
__device__ __forceinline__ ull bcast2(float a) {
    ull r;
    asm("mov.b64 %0, {%1, %1};" : "=l"(r) : "f"(a));
    return r;
}
__device__ __forceinline__ ull pack2(float lo, float hi) {
    ull r;
    asm("mov.b64 %0, {%1, %2};" : "=l"(r) : "f"(lo), "f"(hi));
    return r;
}
__device__ __forceinline__ void fma2(ull& c, ull a, ull b) {
    asm("fma.rn.f32x2 %0, %1, %2, %0;" : "+l"(c) : "l"(a), "l"(b));
}
__device__ __forceinline__ ull add2(ull a, ull b) {
    ull r;
    asm("add.rn.f32x2 %0, %1, %2;" : "=l"(r) : "l"(a), "l"(b));
    return r;
}
__device__ __forceinline__ ull mul2(ull a, ull b) {
    ull r;
    asm("mul.rn.f32x2 %0, %1, %2;" : "=l"(r) : "l"(a), "l"(b));
    return r;
}
__device__ __forceinline__ void unpack2(ull v, float& lo, float& hi) {
    asm("mov.b64 {%0, %1}, %2;" : "=f"(lo), "=f"(hi) : "l"(v));
}
__device__ __forceinline__ int popc4(uint4 a, uint4 b) {
    return __popc(a.x ^ b.x) + __popc(a.y ^ b.y) + __popc(a.z ^ b.z) + __popc(a.w ^ b.w);
}
__device__ __forceinline__ uint32_t smem_u32(const void* p) {
    uint32_t a;
    asm("{ .reg .u64 t; cvta.to.shared.u64 t, %1; cvt.u32.u64 %0, t; }" : "=r"(a) : "l"(p));
    return a;
}
__device__ __forceinline__ void cp16(uint32_t d, const void* s) {
    asm volatile("cp.async.ca.shared.global [%0], [%1], 16;" :: "r"(d), "l"(s) : "memory");
}
#define CP_COMMIT() asm volatile("cp.async.commit_group;" ::: "memory")
#define CP_WAIT(n)  asm volatile("cp.async.wait_group %0;" :: "n"(n) : "memory")

// ---------------- mega: hist [0,260) + prep [260,300) + binact [300,16300) --
__global__ __launch_bounds__(512) void mega_kernel(
    const float* __restrict__ x,
    const int* __restrict__ dst1, const int* __restrict__ dst2,
    const float* __restrict__ wr1, const float* __restrict__ wroot1,
    const float* __restrict__ wr2, const float* __restrict__ wroot2,
    const float* __restrict__ brel1, const float* __restrict__ broot1,
    const float* __restrict__ brel2, const float* __restrict__ broot2)
{
    unsigned bid = blockIdx.x;
    int tid = threadIdx.x;
    if (bid < 260u) {                       // ---- hist ----
        unsigned t = bid * 512u + tid;
        if (t < NE1 / 4) {
            int4 d = ((const int4*)dst1)[t];
            atomicAdd(&g_cnt1[d.x], 1u); atomicAdd(&g_cnt1[d.y], 1u);
            atomicAdd(&g_cnt1[d.z], 1u); atomicAdd(&g_cnt1[d.w], 1u);
        } else {
            unsigned j = t - NE1 / 4;
            if (j < NE2 / 4) {
                int4 d = ((const int4*)dst2)[j];
                atomicAdd(&g_cnt2[d.x], 1u); atomicAdd(&g_cnt2[d.y], 1u);
                atomicAdd(&g_cnt2[d.z], 1u); atomicAdd(&g_cnt2[d.w], 1u);
            }
        }
        return;
    }
    if (bid < 300u) {                       // ---- prep ----
        int t = (bid - 260u) * 512 + tid;   // 0..20479
        if (t < HID) g_bsum1[t] = brel1[t] + broot1[t];
        if (t < OUT_F) g_bsum2[t] = brel2[t] + broot2[t];
        int w = t >> 5;
        int L = tid & 31;
        if (w < HID) {                      // rel1 -> fp32 w_hat transposed
            int k = w;
            float4 v = *(const float4*)(wr1 + (size_t)k * IN_F + 4 * L);
            float s = warp_sum(fabsf(v.x) + fabsf(v.y) + fabsf(v.z) + fabsf(v.w));
            float m = s * (1.f / IN_F);
            float vv[4] = {v.x, v.y, v.z, v.w};
#pragma unroll
            for (int q = 0; q < 4; q++) {
                int j = 4 * L + q;
                g_bt1[j * HID + k] = vv[q] > 0.f ? m : (vv[q] < 0.f ? -m : 0.f);
            }
        } else if (w < 2 * HID) {           // root1 -> masks (binact layout) + mroot
            int k = w - HID;
            int cb = 8 * (L & 15) + (L >> 4);
            float f0 = wroot1[(size_t)k * IN_F + cb];
            float f1 = wroot1[(size_t)k * IN_F + cb + 2];
            float f2 = wroot1[(size_t)k * IN_F + cb + 4];
            float f3 = wroot1[(size_t)k * IN_F + cb + 6];
            float s = warp_sum(fabsf(f0) + fabsf(f1) + fabsf(f2) + fabsf(f3));
            unsigned b0 = __ballot_sync(0xffffffffu, f0 > 0.f);
            unsigned b1 = __ballot_sync(0xffffffffu, f1 > 0.f);
            unsigned b2 = __ballot_sync(0xffffffffu, f2 > 0.f);
            unsigned b3 = __ballot_sync(0xffffffffu, f3 > 0.f);
            if (L == 0) {
                g_mroot1[k] = s * (1.f / IN_F);
                g_wmask1[k] = make_uint4(b0, b1, b2, b3);
            }
        } else if (w < 2 * HID + OUT_F) {   // rel2 -> fp32 bt2
            int k = w - 2 * HID;
            float4 u = *(const float4*)(wr2 + (size_t)k * HID + 8 * L);
            float4 v = *(const float4*)(wr2 + (size_t)k * HID + 8 * L + 4);
            float s = warp_sum(fabsf(u.x) + fabsf(u.y) + fabsf(u.z) + fabsf(u.w) +
                               fabsf(v.x) + fabsf(v.y) + fabsf(v.z) + fabsf(v.w));
            float m = s * (1.f / HID);
            float vv[8] = {u.x, u.y, u.z, u.w, v.x, v.y, v.z, v.w};
#pragma unroll
            for (int q = 0; q < 8; q++) {
                int j = 8 * L + q;
                g_bt2[j * OUT_F + k] = vv[q] > 0.f ? m : (vv[q] < 0.f ? -m : 0.f);
            }
        } else if (w < 2 * HID + 2 * OUT_F) { // root2 -> masks: word q bit L = col 32q+L
            int k = w - 2 * HID - OUT_F;
            float s = 0.f;
            unsigned b[8];
#pragma unroll
            for (int q = 0; q < 8; q++) {
                float f = wroot2[(size_t)k * HID + 32 * q + L];
                s += fabsf(f);
                b[q] = __ballot_sync(0xffffffffu, f > 0.f);
            }
            s = warp_sum(s);
            if (L == 0) {
                g_mroot2[k] = s * (1.f / HID);
#pragma unroll
                for (int q = 0; q < 8; q++) g_wmask2[k * 8 + q] = b[q];
            }
        }
        return;
    }
    // ---- binact1: 2 rows per warp (16 lanes x 8 elems), f32x2 lane math ----
    int w = tid >> 5, L = tid & 31;
    int hl = L & 15, ph = L >> 4;
    int row = (bid - 300u) * 32 + 2 * w + ph;
    const float* xr = x + (size_t)row * IN_F + 8 * hl;
    float4 v1 = *(const float4*)xr;
    float4 v2 = *(const float4*)(xr + 4);
    ull p01 = pack2(v1.x, v1.y), p23 = pack2(v1.z, v1.w);
    ull p45 = pack2(v2.x, v2.y), p67 = pack2(v2.z, v2.w);
    ull s2 = add2(add2(p01, p23), add2(p45, p67));
    ull q2 = mul2(p01, p01);
    fma2(q2, p23, p23);
    fma2(q2, p45, p45);
    fma2(q2, p67, p67);
    float sl, sh, ql, qh;
    unpack2(s2, sl, sh);
    unpack2(q2, ql, qh);
    float s = half_sum(sl + sh);
    float sq = half_sum(ql + qh);
    float mu = s * (1.f / 128.f);
    float var = (sq - 128.f * mu * mu) * (1.f / 127.f);
    float sd = sqrtf(fmaxf(var, 0.f));
    ull nmu2 = bcast2(-mu);
    ull d01 = add2(p01, nmu2), d23 = add2(p23, nmu2);
    ull d45 = add2(p45, nmu2), d67 = add2(p67, nmu2);
    float e0, e1, e2, e3, e4, e5, e6, e7;
    unpack2(d01, e0, e1); unpack2(d23, e2, e3);
    unpack2(d45, e4, e5); unpack2(d67, e6, e7);
    float l1 = fabsf(e0) + fabsf(e1) + fabsf(e2) + fabsf(e3) +
               fabsf(e4) + fabsf(e5) + fabsf(e6) + fabsf(e7);
    l1 = half_sum(l1);
    float a = (l1 * (1.f / 128.f)) / (sd + EPSV);
    unsigned b0 = __ballot_sync(0xffffffffu, v1.x > mu);
    unsigned b1 = __ballot_sync(0xffffffffu, v1.y > mu);
    unsigned b2 = __ballot_sync(0xffffffffu, v1.z > mu);
    unsigned b3 = __ballot_sync(0xffffffffu, v1.w > mu);
    unsigned b4 = __ballot_sync(0xffffffffu, v2.x > mu);
    unsigned b5 = __ballot_sync(0xffffffffu, v2.y > mu);
    unsigned b6 = __ballot_sync(0xffffffffu, v2.z > mu);
    unsigned b7 = __ballot_sync(0xffffffffu, v2.w > mu);
    if (L == 0) {
        g_alpha1[row] = a;
        g_mask1[row] = make_uint4((b0 & 0xFFFFu) | (b1 << 16),
                                  (b2 & 0xFFFFu) | (b3 << 16),
                                  (b4 & 0xFFFFu) | (b5 << 16),
                                  (b6 & 0xFFFFu) | (b7 << 16));
    } else if (L == 16) {
        g_alpha1[row] = a;
        g_mask1[row] = make_uint4((b0 >> 16) | (b1 & 0xFFFF0000u),
                                  (b2 >> 16) | (b3 & 0xFFFF0000u),
                                  (b4 >> 16) | (b5 & 0xFFFF0000u),
                                  (b6 >> 16) | (b7 & 0xFFFF0000u));
    }
}

// ---------------- scan (both layers); re-zeroes cnt for replay ----------------
__global__ __launch_bounds__(1024) void scan12_kernel() {
    int layer = blockIdx.x;
    unsigned* cnt = layer ? g_cnt2 : g_cnt1;
    unsigned* off = layer ? g_off2 : g_off1;
    unsigned* cur = layer ? g_cur2 : g_cur1;
    int n = layer ? NN2 : NN1;
    int per = n >> 10;
    int t = threadIdx.x;
    int s0 = t * per;
    unsigned loc[20];
    unsigned tot = 0;
    for (int i = 0; i < per; i++) { loc[i] = cnt[s0 + i]; cnt[s0 + i] = 0u; tot += loc[i]; }
    unsigned ws = tot;
#pragma unroll
    for (int o = 1; o < 32; o <<= 1) {
        unsigned u = __shfl_up_sync(0xffffffffu, ws, o);
        if ((t & 31) >= o) ws += u;
    }
    __shared__ unsigned wsum[32];
    if ((t & 31) == 31) wsum[t >> 5] = ws;
    __syncthreads();
    if (t < 32) {
        unsigned v2 = wsum[t], sc = v2;
#pragma unroll
        for (int o = 1; o < 32; o <<= 1) {
            unsigned u = __shfl_up_sync(0xffffffffu, sc, o);
            if (t >= o) sc += u;
        }
        wsum[t] = sc - v2;
    }
    __syncthreads();
    unsigned run = wsum[t >> 5] + ws - tot;
    for (int i = 0; i < per; i++) {
        off[s0 + i] = run;
        cur[s0 + i] = run;
        run += loc[i];
    }
    if (t == 1023) off[n] = run;
}

// ---------------- placement (4 edges/thread) ----------------
__global__ __launch_bounds__(512) void place12_kernel(
    const int* __restrict__ dst1, const int* __restrict__ src1,
    const int* __restrict__ dst2, const int* __restrict__ src2)
{
    unsigned t = blockIdx.x * 512u + threadIdx.x;
    if (t < NE1 / 4) {
        int4 d = ((const int4*)dst1)[t];
        int4 s = ((const int4*)src1)[t];
        g_srcs1[atomicAdd(&g_cur1[d.x], 1u)] = s.x;
        g_srcs1[atomicAdd(&g_cur1[d.y], 1u)] = s.y;
        g_srcs1[atomicAdd(&g_cur1[d.z], 1u)] = s.z;
        g_srcs1[atomicAdd(&g_cur1[d.w], 1u)] = s.w;
    } else {
        unsigned j = t - NE1 / 4;
        if (j < NE2 / 4) {
            int4 d = ((const int4*)dst2)[j];
            int4 s = ((const int4*)src2)[j];
            g_srcs2[atomicAdd(&g_cur2[d.x], 1u)] = s.x;
            g_srcs2[atomicAdd(&g_cur2[d.y], 1u)] = s.y;
            g_srcs2[atomicAdd(&g_cur2[d.z], 1u)] = s.z;
            g_srcs2[atomicAdd(&g_cur2[d.w], 1u)] = s.w;
        }
    }
}

// ---------------- agg1: one dst per warp; sign-trick accumulation ----------
__global__ __launch_bounds__(256) void agg1_kernel() {
    int d = (blockIdx.x * 256 + threadIdx.x) >> 5;
    int L = threadIdx.x & 31;
    unsigned beg = g_off1[d], end = g_off1[d + 1];
    float a0 = 0.f, a1 = 0.f, a2 = 0.f, a3 = 0.f, asum = 0.f;
    for (unsigned base = beg; base < end; base += 32u) {
        unsigned e = base + L;
        float al = 0.f;
        uint4 m = make_uint4(0u, 0u, 0u, 0u);
        if (e < end) {
            int s = g_srcs1[e];
            al = g_alpha1[s];
            m = g_mask1[s];
        }
        unsigned n = min(32u, end - base);
        for (unsigned t2 = 0; t2 < n; t2++) {
            float av = __shfl_sync(0xffffffffu, al, t2);
            unsigned mx = __shfl_sync(0xffffffffu, m.x, t2);
            unsigned my = __shfl_sync(0xffffffffu, m.y, t2);
            unsigned mz = __shfl_sync(0xffffffffu, m.z, t2);
            unsigned mw = __shfl_sync(0xffffffffu, m.w, t2);
            asum += av;
            if ((mx >> L) & 1u) a0 += av;
            if ((my >> L) & 1u) a1 += av;
            if ((mz >> L) & 1u) a2 += av;
            if ((mw >> L) & 1u) a3 += av;
        }
    }
    unsigned c = end - beg;
    float inv = 1.f / (float)(c == 0u ? 1u : c);
    a0 = (2.f * a0 - asum) * inv;
    a1 = (2.f * a1 - asum) * inv;
    a2 = (2.f * a2 - asum) * inv;
    a3 = (2.f * a3 - asum) * inv;
    int cb = 8 * (L & 15) + (L >> 4);
    float* o = g_agg1 + (size_t)d * IN_F;
    o[cb]     = a0;
    o[cb + 2] = a1;
    o[cb + 4] = a2;
    o[cb + 6] = a3;
}

// ---------------- gemm1 (R12 tiling, 32-k double-buffered B) ----------------
// 640 blocks x 512 thr, 2/SM. Tile M=32 x N=256; 4 rows x 4 cols per thread.
#define SMA   0                        // float As[32][128]      16384 B
#define SMB   16384                    // float Bs[2][32][256]   65536 B
#define SMRS  81920                    // float2 redS[32][2]     512 B
#define SMRL  82432                    // float  redL[32][2]     256 B
#define SMSK  82688                    // unsigned smask[32][8]  1024 B
#define SMT   83712

__global__ __launch_bounds__(512, 2) void gemm1_kernel() {
    extern __shared__ char sm[];
    float (*As)[128]     = (float (*)[128])(sm + SMA);
    float2 (*redS)[2]    = (float2 (*)[2])(sm + SMRS);
    float (*redL)[2]     = (float (*)[2])(sm + SMRL);
    unsigned (*smask)[8] = (unsigned (*)[8])(sm + SMSK);
    uint32_t sb = smem_u32(sm);
    int tid = threadIdx.x;
    int w = tid >> 5, L = tid & 31;
    int p = w >> 1, h = w & 1;
    int bm = blockIdx.x * 32;
    if (tid < 256) smask[tid >> 3][tid & 7] = 0u;

    // stage A once: 32 rows x 128 k (2 float4 per thread)
#pragma unroll
    for (int r = 0; r < 2; r++) {
        int idx = tid + r * 512;
        int row = idx >> 5, q = idx & 31;
        *(float4*)&As[row][4 * q] =
            *(const float4*)(g_agg1 + (size_t)(bm + row) * IN_F + 4 * q);
    }
    // prefetch B chunk 0 (32 k x 256 cols = 2048 float4s -> 4 per thread)
#pragma unroll
    for (int r = 0; r < 4; r++) {
        int idx = tid + r * 512;
        int kk = idx >> 6, n4 = idx & 63;
        cp16(sb + SMB + (unsigned)kk * 1024u + 16u * n4,
             g_bt1 + (size_t)kk * HID + 4 * n4);
    }
    CP_COMMIT();

    ull acc[4][2];
#pragma unroll
    for (int i = 0; i < 4; i++) { acc[i][0] = 0ull; acc[i][1] = 0ull; }

    for (int k0 = 0; k0 < 4; k0++) {
        int cur = k0 & 1;
        if (k0 < 3) {
#pragma unroll
            for (int r = 0; r < 4; r++) {
                int idx = tid + r * 512;
                int kk = idx >> 6, n4 = idx & 63;
                cp16(sb + SMB + (unsigned)((cur ^ 1) * 32 + kk) * 1024u + 16u * n4,
                     g_bt1 + (size_t)((k0 + 1) * 32 + kk) * HID + 4 * n4);
            }
            CP_COMMIT();
            CP_WAIT(1);
        } else {
            CP_WAIT(0);
        }
        __syncthreads();
        const char* bbase = sm + SMB + (unsigned)cur * 32768u;
#pragma unroll
        for (int kk4 = 0; kk4 < 8; kk4++) {
            float4 a4[4];
#pragma unroll
            for (int i = 0; i < 4; i++)
                a4[i] = *(const float4*)&As[p * 4 + i][k0 * 32 + 4 * kk4];
#pragma unroll
            for (int kk = 0; kk < 4; kk++) {
                ulonglong2 bv = *(const ulonglong2*)(bbase +
                    (unsigned)(4 * kk4 + kk) * 1024u + (unsigned)(h * 128 + 4 * L) * 4u);
#pragma unroll
                for (int i = 0; i < 4; i++) {
                    float av = kk == 0 ? a4[i].x : kk == 1 ? a4[i].y
                             : kk == 2 ? a4[i].z : a4[i].w;
                    ull ad = bcast2(av);
                    fma2(acc[i][0], ad, bv.x);
                    fma2(acc[i][1], ad, bv.y);
                }
            }
        }
        __syncthreads();
    }

    // ---- epilogue: root + bias + relu + binact2 ----
    int cbase = h * 128 + 4 * L;
    float mr[4], bsv[4];
    uint4 wm[4];
#pragma unroll
    for (int j = 0; j < 4; j++) {
        mr[j] = g_mroot1[cbase + j];
        bsv[j] = g_bsum1[cbase + j];
        wm[j] = g_wmask1[cbase + j];
    }
    float v[4][4];
#pragma unroll
    for (int i = 0; i < 4; i++) {
        int row = bm + p * 4 + i;
        float al = g_alpha1[row];
        uint4 mx = g_mask1[row];
        unpack2(acc[i][0], v[i][0], v[i][1]);
        unpack2(acc[i][1], v[i][2], v[i][3]);
        float ss = 0.f, qq = 0.f;
#pragma unroll
        for (int j = 0; j < 4; j++) {
            int pc = popc4(mx, wm[j]);
            float val = v[i][j] + bsv[j] + al * mr[j] * (float)(128 - 2 * pc);
            val = fmaxf(val, 0.f);
            v[i][j] = val;
            ss += val;
            qq = fmaf(val, val, qq);
        }
        ss = warp_sum(ss);
        qq = warp_sum(qq);
        if (L == 0) redS[p * 4 + i][h] = make_float2(ss, qq);
    }
    __syncthreads();
#pragma unroll
    for (int i = 0; i < 4; i++) {
        float2 rA = redS[p * 4 + i][0], rB = redS[p * 4 + i][1];
        float mu = (rA.x + rB.x) * (1.f / 256.f);
        float l1 = 0.f;
        unsigned bits = 0u;
#pragma unroll
        for (int j = 0; j < 4; j++) {
            float d = v[i][j] - mu;
            l1 += fabsf(d);
            if (d > 0.f) bits |= 1u << ((L & 7) * 4 + j);
        }
        l1 = warp_sum(l1);
        if (L == 0) redL[p * 4 + i][h] = l1;
        atomicOr(&smask[p * 4 + i][h * 4 + (L >> 3)], bits);
    }
    __syncthreads();
    if (tid < 32) {
        int r = tid;
        float2 rA = redS[r][0], rB = redS[r][1];
        float S = rA.x + rB.x, Q = rA.y + rB.y;
        float mu = S * (1.f / 256.f);
        float var = (Q - 256.f * mu * mu) * (1.f / 255.f);
        float sd = sqrtf(fmaxf(var, 0.f));
        float L1 = redL[r][0] + redL[r][1];
        g_alpha2[bm + r] = (L1 * (1.f / 256.f)) / (sd + EPSV);
        uint4* mp = (uint4*)(g_mask2 + (size_t)(bm + r) * 8);
        mp[0] = make_uint4(smask[r][0], smask[r][1], smask[r][2], smask[r][3]);
        mp[1] = make_uint4(smask[r][4], smask[r][5], smask[r][6], smask[r][7]);
    }
}

// ---------------- fused agg2 + gemm2 + root + log_softmax ----------------
__global__ __launch_bounds__(256) void aggfinal_kernel(float* __restrict__ out) {
    __shared__ float sa[8][264];
    __shared__ float bts[64][72];
    int tid = threadIdx.x;
    int w = tid >> 5, L = tid & 31;
    int d = blockIdx.x * 8 + w;

    unsigned beg = g_off2[d], end = g_off2[d + 1];
    float a[8];
    float asum = 0.f;
#pragma unroll
    for (int q = 0; q < 8; q++) a[q] = 0.f;
    for (unsigned base = beg; base < end; base += 32u) {
        unsigned e = base + L;
        float al = 0.f;
        uint4 m1 = make_uint4(0u, 0u, 0u, 0u), m2 = m1;
        if (e < end) {
            int s = g_srcs2[e];
            al = g_alpha2[s];
            const uint4* mp = (const uint4*)(g_mask2 + (size_t)s * 8);
            m1 = mp[0]; m2 = mp[1];
        }
        unsigned n = min(32u, end - base);
        for (unsigned t = 0; t < n; t++) {
            float av = __shfl_sync(0xffffffffu, al, t);
            unsigned mw0 = __shfl_sync(0xffffffffu, m1.x, t);
            unsigned mw1 = __shfl_sync(0xffffffffu, m1.y, t);
            unsigned mw2 = __shfl_sync(0xffffffffu, m1.z, t);
            unsigned mw3 = __shfl_sync(0xffffffffu, m1.w, t);
            unsigned mw4 = __shfl_sync(0xffffffffu, m2.x, t);
            unsigned mw5 = __shfl_sync(0xffffffffu, m2.y, t);
            unsigned mw6 = __shfl_sync(0xffffffffu, m2.z, t);
            unsigned mw7 = __shfl_sync(0xffffffffu, m2.w, t);
            asum += av;
            if ((mw0 >> L) & 1u) a[0] += av;
            if ((mw1 >> L) & 1u) a[1] += av;
            if ((mw2 >> L) & 1u) a[2] += av;
            if ((mw3 >> L) & 1u) a[3] += av;
            if ((mw4 >> L) & 1u) a[4] += av;
            if ((mw5 >> L) & 1u) a[5] += av;
            if ((mw6 >> L) & 1u) a[6] += av;
            if ((mw7 >> L) & 1u) a[7] += av;
        }
    }
    unsigned c = end - beg;
    float inv = 1.f / (float)(c == 0u ? 1u : c);
#pragma unroll
    for (int q = 0; q < 8; q++) sa[w][32 * q + L] = (2.f * a[q] - asum) * inv;

    float acc0 = 0.f, acc1 = 0.f;
    for (int j0 = 0; j0 < HID; j0 += 64) {
        __syncthreads();
#pragma unroll
        for (int r = 0; r < 4; r++) {
            int f = tid + r * 256;
            int jj = f >> 4, c4 = f & 15;
            *(float4*)&bts[jj][c4 * 4] =
                *(const float4*)(g_bt2 + (size_t)(j0 + jj) * OUT_F + 4 * c4);
        }
        __syncthreads();
#pragma unroll 8
        for (int jj = 0; jj < 64; jj++) {
            float av = sa[w][j0 + jj];
            acc0 = fmaf(av, bts[jj][L], acc0);
            acc1 = fmaf(av, bts[jj][L + 32], acc1);
        }
    }

    int c0 = L, c1 = L + 32;
    const uint4* mp = (const uint4*)(g_mask2 + (size_t)d * 8);
    uint4 ma = mp[0], mb = mp[1];
    float al = g_alpha2[d];
    const uint4* w0 = (const uint4*)(g_wmask2 + c0 * 8);
    const uint4* w1 = (const uint4*)(g_wmask2 + c1 * 8);
    int p0 = popc4(ma, w0[0]) + popc4(mb, w0[1]);
    int p1 = popc4(ma, w1[0]) + popc4(mb, w1[1]);
    float v0 = acc0 + g_bsum2[c0] + al * g_mroot2[c0] * (float)(256 - 2 * p0);
    float v1 = acc1 + g_bsum2[c1] + al * g_mroot2[c1] * (float)(256 - 2 * p1);
    float mx = warp_max(fmaxf(v0, v1));
    float s = warp_sum(expf(v0 - mx) + expf(v1 - mx));
    float lse = mx + logf(s);
    out[(size_t)d * OUT_F + c0] = v0 - lse;
    out[(size_t)d * OUT_F + c1] = v1 - lse;
}

// ---------------- launcher ----------------
extern "C" void kernel_launch(void* const* d_in, const int* in_sizes, int n_in,
                              void* d_out, int out_size) {
    const float* x       = (const float*)d_in[0];
    const int*   src1    = (const int*)d_in[1];
    const int*   dst1    = (const int*)d_in[2];
    const int*   src2    = (const int*)d_in[3];
    const int*   dst2    = (const int*)d_in[4];
    const float* w_rel1  = (const float*)d_in[5];
    const float* b_rel1  = (const float*)d_in[6];
    const float* w_root1 = (const float*)d_in[7];
    const float* b_root1 = (const float*)d_in[8];
    const float* w_rel2  = (const float*)d_in[9];
    const float* b_rel2  = (const float*)d_in[10];
    const float* w_root2 = (const float*)d_in[11];
    const float* b_root2 = (const float*)d_in[12];
    float* out = (float*)d_out;

    static int once = 0;
    if (!once) {
        cudaFuncSetAttribute(gemm1_kernel,
                             cudaFuncAttributeMaxDynamicSharedMemorySize, SMT);
        once = 1;
    }

    mega_kernel<<<16300, 512>>>(x, dst1, dst2, w_rel1, w_root1, w_rel2, w_root2,
                                b_rel1, b_root1, b_rel2, b_root2);
    scan12_kernel<<<2, 1024>>>();
    place12_kernel<<<260, 512>>>(dst1, src1, dst2, src2);
    agg1_kernel<<<NN1 * 32 / 256, 256>>>();
    gemm1_kernel<<<NN1 / 32, 512, SMT>>>();
    aggfinal_kernel<<<NN2 / 8, 256>>>(out);
    (void)in_sizes; (void)n_in; (void)out_size;
}